// round 2
// baseline (speedup 1.0000x reference)
#include <cuda_runtime.h>
#include <cuda_bf16.h>

#define N_NODES 400000
#define N_EDGES 6400000
#define N_GRAPHS 20000
#define F_IN 11
#define HID 32

// ---------------- scratch (static device globals; no allocs) ----------------
__device__ __align__(16) float g_bufA[(size_t)N_NODES * HID];   // h (gather source)
__device__ __align__(16) float g_bufB[(size_t)N_NODES * HID];   // agg (scatter target)
__device__ float g_dinv[N_NODES];
__device__ int   g_deg[N_NODES];
__device__ float g_norm[N_EDGES];
__device__ __align__(16) float g_sums[(size_t)N_GRAPHS * HID];
__device__ float g_cnt[N_GRAPHS];

// ---------------- helpers ----------------
__device__ __forceinline__ void red_add_v4(float* p, float a, float b, float c, float d) {
    asm volatile("red.global.add.v4.f32 [%0], {%1,%2,%3,%4};"
                 :: "l"(p), "f"(a), "f"(b), "f"(c), "f"(d) : "memory");
}
__device__ __forceinline__ void red_add_f32(float* p, float v) {
    asm volatile("red.global.add.f32 [%0], %1;" :: "l"(p), "f"(v) : "memory");
}

// ---------------- kernels ----------------
__global__ void k_init_deg() {
    int i = blockIdx.x * blockDim.x + threadIdx.x;
    if (i < N_NODES) g_deg[i] = 1;   // self-loop
}

__global__ void k_count_deg(const int* __restrict__ ei) {
    int e = blockIdx.x * blockDim.x + threadIdx.x;
    if (e < N_EDGES) atomicAdd(&g_deg[ei[N_EDGES + e]], 1);   // dst row
}

__global__ void k_dinv() {
    int i = blockIdx.x * blockDim.x + threadIdx.x;
    if (i < N_NODES) g_dinv[i] = rsqrtf((float)g_deg[i]);
}

__global__ void k_norm(const int* __restrict__ ei) {
    int e = blockIdx.x * blockDim.x + threadIdx.x;
    if (e < N_EDGES) g_norm[e] = g_dinv[ei[e]] * g_dinv[ei[N_EDGES + e]];
}

// h1 = x @ W1 ; also init agg1 with self-loop contribution h1 * dinv^2
__global__ void k_gemm1(const float* __restrict__ x, const float* __restrict__ W1) {
    int warp = (blockIdx.x * blockDim.x + threadIdx.x) >> 5;
    int lane = threadIdx.x & 31;
    if (warp >= N_NODES) return;
    float xi = (lane < F_IN) ? x[warp * F_IN + lane] : 0.0f;
    float acc = 0.0f;
#pragma unroll
    for (int k = 0; k < F_IN; k++)
        acc = fmaf(__shfl_sync(0xffffffffu, xi, k), W1[k * HID + lane], acc);
    g_bufA[(size_t)warp * HID + lane] = acc;
    float di = g_dinv[warp];
    g_bufB[(size_t)warp * HID + lane] = acc * di * di;
}

// edge pass: agg[dst] += h[src] * norm   (gather bufA, scatter bufB)
__global__ void k_edge(const int* __restrict__ ei) {
    int t = blockIdx.x * blockDim.x + threadIdx.x;
    int e = t >> 3;
    if (e >= N_EDGES) return;
    int f = (t & 7) << 2;
    int src = ei[e];
    int dst = ei[N_EDGES + e];
    float nrm = g_norm[e];
    const float4 h = *(const float4*)&g_bufA[(size_t)src * HID + f];
    float* p = &g_bufB[(size_t)dst * HID + f];
    red_add_v4(p, h.x * nrm, h.y * nrm, h.z * nrm, h.w * nrm);
}

// h2 = relu(agg1 + b1) @ W2 ; also init agg2 with self-loop contribution
__global__ void k_gemm2(const float* __restrict__ b1, const float* __restrict__ W2) {
    int warp = (blockIdx.x * blockDim.x + threadIdx.x) >> 5;
    int lane = threadIdx.x & 31;
    if (warp >= N_NODES) return;
    float v = g_bufB[(size_t)warp * HID + lane] + b1[lane];
    v = fmaxf(v, 0.0f);
    float acc = 0.0f;
#pragma unroll
    for (int k = 0; k < HID; k++)
        acc = fmaf(__shfl_sync(0xffffffffu, v, k), W2[k * HID + lane], acc);
    g_bufA[(size_t)warp * HID + lane] = acc;
    float di = g_dinv[warp];
    g_bufB[(size_t)warp * HID + lane] = acc * di * di;
}

__global__ void k_zero_pool() {
    int t = blockIdx.x * blockDim.x + threadIdx.x;
    if (t < N_GRAPHS * HID) g_sums[t] = 0.0f;
    if (t < N_GRAPHS) g_cnt[t] = 0.0f;
}

// pool raw agg2 (bias reconstructed in MLP)
__global__ void k_pool(const int* __restrict__ batch) {
    int t = blockIdx.x * blockDim.x + threadIdx.x;
    int i = t >> 3;
    if (i >= N_NODES) return;
    int c = (t & 7) << 2;
    int g = batch[i];
    const float4 v = *(const float4*)&g_bufB[(size_t)i * HID + c];
    red_add_v4(&g_sums[(size_t)g * HID + c], v.x, v.y, v.z, v.w);
    if (c == 0) red_add_f32(&g_cnt[g], 1.0f);
}

__global__ void k_mlp(const float* __restrict__ b2,
                      const float* __restrict__ fcW1, const float* __restrict__ fcb1,
                      const float* __restrict__ fcW2, const float* __restrict__ fcb2,
                      float* __restrict__ out) {
    int warp = (blockIdx.x * blockDim.x + threadIdx.x) >> 5;
    int lane = threadIdx.x & 31;
    if (warp >= N_GRAPHS) return;
    float cnt = g_cnt[warp];
    float inv = 1.0f / fmaxf(cnt, 1.0f);
    // pooled = (sum(agg2) + cnt*b2) / max(cnt,1)  == mean(agg2 + b2)
    float p = (g_sums[(size_t)warp * HID + lane] + cnt * b2[lane]) * inv;
    float acc = fcb1[lane];
#pragma unroll
    for (int k = 0; k < HID; k++)
        acc = fmaf(__shfl_sync(0xffffffffu, p, k), fcW1[k * HID + lane], acc);
    acc = fmaxf(acc, 0.0f);
    float o = acc * fcW2[lane];
#pragma unroll
    for (int off = 16; off > 0; off >>= 1)
        o += __shfl_xor_sync(0xffffffffu, o, off);
    if (lane == 0) out[warp] = o + fcb2[0];
}

// ---------------- launch ----------------
extern "C" void kernel_launch(void* const* d_in, const int* in_sizes, int n_in,
                              void* d_out, int out_size) {
    const float* x     = (const float*)d_in[0];
    const int*   ei    = (const int*)  d_in[1];
    const int*   batch = (const int*)  d_in[2];
    const float* W1    = (const float*)d_in[3];
    const float* b1    = (const float*)d_in[4];
    const float* W2    = (const float*)d_in[5];
    const float* b2    = (const float*)d_in[6];
    const float* fcW1  = (const float*)d_in[7];
    const float* fcb1  = (const float*)d_in[8];
    const float* fcW2  = (const float*)d_in[9];
    const float* fcb2  = (const float*)d_in[10];
    float* out = (float*)d_out;

    const int TB = 256;
    k_init_deg <<<(N_NODES + TB - 1) / TB, TB>>>();
    k_count_deg<<<(N_EDGES + TB - 1) / TB, TB>>>(ei);
    k_dinv     <<<(N_NODES + TB - 1) / TB, TB>>>();
    k_norm     <<<(N_EDGES + TB - 1) / TB, TB>>>(ei);

    int gemm_grid = (N_NODES * 32 + TB - 1) / TB;
    int edge_grid = (N_EDGES * 8 + TB - 1) / TB;

    k_gemm1<<<gemm_grid, TB>>>(x, W1);
    k_edge <<<edge_grid, TB>>>(ei);
    k_gemm2<<<gemm_grid, TB>>>(b1, W2);
    k_edge <<<edge_grid, TB>>>(ei);

    k_zero_pool<<<(N_GRAPHS * HID + TB - 1) / TB, TB>>>();
    k_pool     <<<(N_NODES * 8 + TB - 1) / TB, TB>>>(batch);
    k_mlp      <<<(N_GRAPHS * 32 + TB - 1) / TB, TB>>>(b2, fcW1, fcb1, fcW2, fcb2, out);
}

// round 3
// speedup vs baseline: 1.2715x; 1.2715x over previous
#include <cuda_runtime.h>
#include <cuda_bf16.h>

#define N_NODES 400000
#define N_EDGES 6400000
#define N_GRAPHS 20000
#define F_IN 11
#define HID 32

#define SCAN_BLK 512
#define N_SCAN_BLOCKS ((N_NODES + SCAN_BLK - 1) / SCAN_BLK)   // 782

// ---------------- scratch (static device globals; no allocs) ----------------
__device__ __align__(16) float g_bufA[(size_t)N_NODES * HID];   // gather source (pre-scaled by dinv)
__device__ __align__(16) float g_bufB[(size_t)N_NODES * HID];   // aggregation result
__device__ float g_dinv[N_NODES];
__device__ int   g_deg[N_NODES];          // edge-only in-degree
__device__ int   g_rowptr[N_NODES];
__device__ int   g_cursor[N_NODES];
__device__ int   g_partial[N_SCAN_BLOCKS];
__device__ int   g_csr_src[N_EDGES];
__device__ __align__(16) float g_sums[(size_t)N_GRAPHS * HID];
__device__ float g_cnt[N_GRAPHS];

// ---------------- helpers ----------------
__device__ __forceinline__ void red_add_v4(float* p, float a, float b, float c, float d) {
    asm volatile("red.global.add.v4.f32 [%0], {%1,%2,%3,%4};"
                 :: "l"(p), "f"(a), "f"(b), "f"(c), "f"(d) : "memory");
}
__device__ __forceinline__ void red_add_f32(float* p, float v) {
    asm volatile("red.global.add.f32 [%0], %1;" :: "l"(p), "f"(v) : "memory");
}

// ---------------- init / histogram ----------------
// one kernel zeroes deg, sums, cnt  (grid covers N_GRAPHS*HID = 640000 >= N_NODES)
__global__ void k_zero() {
    int t = blockIdx.x * blockDim.x + threadIdx.x;
    if (t < N_GRAPHS * HID) g_sums[t] = 0.0f;
    if (t < N_GRAPHS)       g_cnt[t]  = 0.0f;
    if (t < N_NODES)        g_deg[t]  = 0;
}

__global__ void k_count_deg(const int* __restrict__ ei) {
    int e = blockIdx.x * blockDim.x + threadIdx.x;
    if (e < N_EDGES) atomicAdd(&g_deg[ei[N_EDGES + e]], 1);   // dst
}

// ---------------- exclusive scan over g_deg -> g_rowptr ----------------
__global__ void k_scan1() {
    __shared__ int wsum[SCAN_BLK / 32];
    int i = blockIdx.x * SCAN_BLK + threadIdx.x;
    int lane = threadIdx.x & 31, w = threadIdx.x >> 5;
    int v = (i < N_NODES) ? g_deg[i] : 0;
    int inc = v;
#pragma unroll
    for (int d = 1; d < 32; d <<= 1) {
        int t = __shfl_up_sync(0xffffffffu, inc, d);
        if (lane >= d) inc += t;
    }
    if (lane == 31) wsum[w] = inc;
    __syncthreads();
    if (threadIdx.x < SCAN_BLK / 32) {   // 16 threads, warp 0
        int s = wsum[threadIdx.x];
        int si = s;
#pragma unroll
        for (int d = 1; d < SCAN_BLK / 32; d <<= 1) {
            int t = __shfl_up_sync(0x0000ffffu, si, d);
            if ((int)threadIdx.x >= d) si += t;
        }
        wsum[threadIdx.x] = si - s;                  // exclusive
        if (threadIdx.x == SCAN_BLK / 32 - 1) g_partial[blockIdx.x] = si;  // block total
    }
    __syncthreads();
    if (i < N_NODES) g_rowptr[i] = inc - v + wsum[w];   // block-local exclusive
}

__global__ void k_scan2() {   // one block of 1024 threads scans 782 partials
    __shared__ int wsum[32];
    int tid = threadIdx.x, lane = tid & 31, w = tid >> 5;
    int v = (tid < N_SCAN_BLOCKS) ? g_partial[tid] : 0;
    int inc = v;
#pragma unroll
    for (int d = 1; d < 32; d <<= 1) {
        int t = __shfl_up_sync(0xffffffffu, inc, d);
        if (lane >= d) inc += t;
    }
    if (lane == 31) wsum[w] = inc;
    __syncthreads();
    if (tid < 32) {
        int s = wsum[tid];
        int si = s;
#pragma unroll
        for (int d = 1; d < 32; d <<= 1) {
            int t = __shfl_up_sync(0xffffffffu, si, d);
            if (tid >= d) si += t;
        }
        wsum[tid] = si - s;
    }
    __syncthreads();
    if (tid < N_SCAN_BLOCKS) g_partial[tid] = inc - v + wsum[w];   // exclusive
}

// finalize rowptr, init cursor, compute dinv (deg+1 for self-loop)
__global__ void k_scan3() {
    int i = blockIdx.x * blockDim.x + threadIdx.x;
    if (i >= N_NODES) return;
    int rp = g_rowptr[i] + g_partial[i / SCAN_BLK];
    g_rowptr[i] = rp;
    g_cursor[i] = rp;
    g_dinv[i] = rsqrtf((float)(g_deg[i] + 1));
}

__global__ void k_fill(const int* __restrict__ ei) {
    int e = blockIdx.x * blockDim.x + threadIdx.x;
    if (e >= N_EDGES) return;
    int dst = ei[N_EDGES + e];
    int slot = atomicAdd(&g_cursor[dst], 1);
    g_csr_src[slot] = ei[e];
}

// ---------------- node GEMMs ----------------
// bufA = (x @ W1) * dinv   (pre-scaled gather buffer)
__global__ void k_gemm1(const float* __restrict__ x, const float* __restrict__ W1) {
    int warp = (blockIdx.x * blockDim.x + threadIdx.x) >> 5;
    int lane = threadIdx.x & 31;
    if (warp >= N_NODES) return;
    float xi = (lane < F_IN) ? x[warp * F_IN + lane] : 0.0f;
    float acc = 0.0f;
#pragma unroll
    for (int k = 0; k < F_IN; k++)
        acc = fmaf(__shfl_sync(0xffffffffu, xi, k), W1[k * HID + lane], acc);
    g_bufA[(size_t)warp * HID + lane] = acc * g_dinv[warp];
}

// bufA = (relu(bufB + b1) @ W2) * dinv
__global__ void k_gemm2(const float* __restrict__ b1, const float* __restrict__ W2) {
    int warp = (blockIdx.x * blockDim.x + threadIdx.x) >> 5;
    int lane = threadIdx.x & 31;
    if (warp >= N_NODES) return;
    float v = fmaxf(g_bufB[(size_t)warp * HID + lane] + b1[lane], 0.0f);
    float acc = 0.0f;
#pragma unroll
    for (int k = 0; k < HID; k++)
        acc = fmaf(__shfl_sync(0xffffffffu, v, k), W2[k * HID + lane], acc);
    g_bufA[(size_t)warp * HID + lane] = acc * g_dinv[warp];
}

// ---------------- CSR aggregation: warp per node, no atomics ----------------
// bufB[i] = dinv[i] * ( bufA[i] + sum_{s in N(i)} bufA[s] )
__global__ void k_aggr() {
    int node = (blockIdx.x * blockDim.x + threadIdx.x) >> 5;
    int lane = threadIdx.x & 31;
    if (node >= N_NODES) return;
    int beg = g_rowptr[node];
    int deg = g_deg[node];
    float acc = g_bufA[(size_t)node * HID + lane];   // self-loop (pre-scaled)
    int j = 0;
    for (; j + 4 <= deg; j += 4) {
        int s0 = g_csr_src[beg + j + 0];
        int s1 = g_csr_src[beg + j + 1];
        int s2 = g_csr_src[beg + j + 2];
        int s3 = g_csr_src[beg + j + 3];
        float a0 = g_bufA[(size_t)s0 * HID + lane];
        float a1 = g_bufA[(size_t)s1 * HID + lane];
        float a2 = g_bufA[(size_t)s2 * HID + lane];
        float a3 = g_bufA[(size_t)s3 * HID + lane];
        acc += (a0 + a1) + (a2 + a3);
    }
    for (; j < deg; j++)
        acc += g_bufA[(size_t)g_csr_src[beg + j] * HID + lane];
    g_bufB[(size_t)node * HID + lane] = acc * g_dinv[node];
}

// ---------------- pooling + MLP ----------------
__global__ void k_pool(const int* __restrict__ batch) {
    int t = blockIdx.x * blockDim.x + threadIdx.x;
    int i = t >> 3;
    if (i >= N_NODES) return;
    int c = (t & 7) << 2;
    int g = batch[i];
    const float4 v = *(const float4*)&g_bufB[(size_t)i * HID + c];
    red_add_v4(&g_sums[(size_t)g * HID + c], v.x, v.y, v.z, v.w);
    if (c == 0) red_add_f32(&g_cnt[g], 1.0f);
}

__global__ void k_mlp(const float* __restrict__ b2,
                      const float* __restrict__ fcW1, const float* __restrict__ fcb1,
                      const float* __restrict__ fcW2, const float* __restrict__ fcb2,
                      float* __restrict__ out) {
    int warp = (blockIdx.x * blockDim.x + threadIdx.x) >> 5;
    int lane = threadIdx.x & 31;
    if (warp >= N_GRAPHS) return;
    float cnt = g_cnt[warp];
    float inv = 1.0f / fmaxf(cnt, 1.0f);
    // pooled = (sum(agg2) + cnt*b2) / max(cnt,1)  == mean(agg2 + b2)
    float p = (g_sums[(size_t)warp * HID + lane] + cnt * b2[lane]) * inv;
    float acc = fcb1[lane];
#pragma unroll
    for (int k = 0; k < HID; k++)
        acc = fmaf(__shfl_sync(0xffffffffu, p, k), fcW1[k * HID + lane], acc);
    acc = fmaxf(acc, 0.0f);
    float o = acc * fcW2[lane];
#pragma unroll
    for (int off = 16; off > 0; off >>= 1)
        o += __shfl_xor_sync(0xffffffffu, o, off);
    if (lane == 0) out[warp] = o + fcb2[0];
}

// ---------------- launch ----------------
extern "C" void kernel_launch(void* const* d_in, const int* in_sizes, int n_in,
                              void* d_out, int out_size) {
    const float* x     = (const float*)d_in[0];
    const int*   ei    = (const int*)  d_in[1];
    const int*   batch = (const int*)  d_in[2];
    const float* W1    = (const float*)d_in[3];
    const float* b1    = (const float*)d_in[4];
    const float* W2    = (const float*)d_in[5];
    const float* b2    = (const float*)d_in[6];
    const float* fcW1  = (const float*)d_in[7];
    const float* fcb1  = (const float*)d_in[8];
    const float* fcW2  = (const float*)d_in[9];
    const float* fcb2  = (const float*)d_in[10];
    float* out = (float*)d_out;

    const int TB = 256;
    const int node_grid = (N_NODES + TB - 1) / TB;
    const int edge_grid = (N_EDGES + TB - 1) / TB;
    const int gemm_grid = (N_NODES * 32 + TB - 1) / TB;

    // CSR build (graph topology identical across both layers)
    k_zero     <<<(N_GRAPHS * HID + TB - 1) / TB, TB>>>();
    k_count_deg<<<edge_grid, TB>>>(ei);
    k_scan1    <<<N_SCAN_BLOCKS, SCAN_BLK>>>();
    k_scan2    <<<1, 1024>>>();
    k_scan3    <<<node_grid, TB>>>();
    k_fill     <<<edge_grid, TB>>>(ei);

    // layer 1
    k_gemm1<<<gemm_grid, TB>>>(x, W1);
    k_aggr <<<gemm_grid, TB>>>();
    // layer 2
    k_gemm2<<<gemm_grid, TB>>>(b1, W2);
    k_aggr <<<gemm_grid, TB>>>();

    // pool + MLP
    k_pool<<<(N_NODES * 8 + TB - 1) / TB, TB>>>(batch);
    k_mlp <<<(N_GRAPHS * 32 + TB - 1) / TB, TB>>>(b2, fcW1, fcb1, fcW2, fcb2, out);
}

// round 4
// speedup vs baseline: 1.5353x; 1.2075x over previous
#include <cuda_runtime.h>
#include <cuda_fp16.h>

#define N_NODES 400000
#define N_EDGES 6400000
#define N_GRAPHS 20000
#define F_IN 11
#define HID 32

#define SCAN_BLK 512
#define N_SCAN_BLOCKS ((N_NODES + SCAN_BLK - 1) / SCAN_BLK)   // 782

// ---------------- scratch (static device globals; no allocs) ----------------
__device__ __align__(16) __half g_hA[(size_t)N_NODES * HID];   // layer-1 gather src (h1*dinv, fp16)
__device__ __align__(16) __half g_hC[(size_t)N_NODES * HID];   // layer-2 gather src (h2*dinv, fp16)
__device__ float g_dinv[N_NODES];
__device__ int   g_deg[N_NODES];          // edge-only in-degree
__device__ int   g_rowptr[N_NODES];
__device__ int   g_cursor[N_NODES];
__device__ int   g_partial[N_SCAN_BLOCKS];
__device__ int   g_csr_src[N_EDGES];
__device__ __align__(16) float g_sums[(size_t)N_GRAPHS * HID];
__device__ float g_cnt[N_GRAPHS];

// ---------------- helpers ----------------
__device__ __forceinline__ void red_add_v4(float* p, float a, float b, float c, float d) {
    asm volatile("red.global.add.v4.f32 [%0], {%1,%2,%3,%4};"
                 :: "l"(p), "f"(a), "f"(b), "f"(c), "f"(d) : "memory");
}
__device__ __forceinline__ void red_add_f32(float* p, float v) {
    asm volatile("red.global.add.f32 [%0], %1;" :: "l"(p), "f"(v) : "memory");
}

// ---------------- init / histogram ----------------
__global__ void k_zero() {
    int t = blockIdx.x * blockDim.x + threadIdx.x;
    if (t < N_GRAPHS * HID) g_sums[t] = 0.0f;
    if (t < N_GRAPHS)       g_cnt[t]  = 0.0f;
    if (t < N_NODES)        g_deg[t]  = 0;
}

__global__ void k_count_deg(const int* __restrict__ ei) {
    int e = blockIdx.x * blockDim.x + threadIdx.x;
    if (e < N_EDGES) atomicAdd(&g_deg[ei[N_EDGES + e]], 1);   // dst
}

// ---------------- exclusive scan over g_deg -> g_rowptr ----------------
__global__ void k_scan1() {
    __shared__ int wsum[SCAN_BLK / 32];
    int i = blockIdx.x * SCAN_BLK + threadIdx.x;
    int lane = threadIdx.x & 31, w = threadIdx.x >> 5;
    int v = (i < N_NODES) ? g_deg[i] : 0;
    int inc = v;
#pragma unroll
    for (int d = 1; d < 32; d <<= 1) {
        int t = __shfl_up_sync(0xffffffffu, inc, d);
        if (lane >= d) inc += t;
    }
    if (lane == 31) wsum[w] = inc;
    __syncthreads();
    if (threadIdx.x < SCAN_BLK / 32) {
        int s = wsum[threadIdx.x];
        int si = s;
#pragma unroll
        for (int d = 1; d < SCAN_BLK / 32; d <<= 1) {
            int t = __shfl_up_sync(0x0000ffffu, si, d);
            if ((int)threadIdx.x >= d) si += t;
        }
        wsum[threadIdx.x] = si - s;
        if (threadIdx.x == SCAN_BLK / 32 - 1) g_partial[blockIdx.x] = si;
    }
    __syncthreads();
    if (i < N_NODES) g_rowptr[i] = inc - v + wsum[w];
}

__global__ void k_scan2() {
    __shared__ int wsum[32];
    int tid = threadIdx.x, lane = tid & 31, w = tid >> 5;
    int v = (tid < N_SCAN_BLOCKS) ? g_partial[tid] : 0;
    int inc = v;
#pragma unroll
    for (int d = 1; d < 32; d <<= 1) {
        int t = __shfl_up_sync(0xffffffffu, inc, d);
        if (lane >= d) inc += t;
    }
    if (lane == 31) wsum[w] = inc;
    __syncthreads();
    if (tid < 32) {
        int s = wsum[tid];
        int si = s;
#pragma unroll
        for (int d = 1; d < 32; d <<= 1) {
            int t = __shfl_up_sync(0xffffffffu, si, d);
            if (tid >= d) si += t;
        }
        wsum[tid] = si - s;
    }
    __syncthreads();
    if (tid < N_SCAN_BLOCKS) g_partial[tid] = inc - v + wsum[w];
}

__global__ void k_scan3() {
    int i = blockIdx.x * blockDim.x + threadIdx.x;
    if (i >= N_NODES) return;
    int rp = g_rowptr[i] + g_partial[i / SCAN_BLK];
    g_rowptr[i] = rp;
    g_cursor[i] = rp;
    g_dinv[i] = rsqrtf((float)(g_deg[i] + 1));
}

__global__ void k_fill(const int* __restrict__ ei) {
    int e = blockIdx.x * blockDim.x + threadIdx.x;
    if (e >= N_EDGES) return;
    int dst = ei[N_EDGES + e];
    int slot = atomicAdd(&g_cursor[dst], 1);
    g_csr_src[slot] = ei[e];
}

// ---------------- layer-1 node GEMM: g_hA = half((x @ W1) * dinv) ----------------
__global__ void k_gemm1(const float* __restrict__ x, const float* __restrict__ W1) {
    int warp = (blockIdx.x * blockDim.x + threadIdx.x) >> 5;
    int lane = threadIdx.x & 31;
    if (warp >= N_NODES) return;
    float xi = (lane < F_IN) ? x[warp * F_IN + lane] : 0.0f;
    float acc = 0.0f;
#pragma unroll
    for (int k = 0; k < F_IN; k++)
        acc = fmaf(__shfl_sync(0xffffffffu, xi, k), W1[k * HID + lane], acc);
    g_hA[(size_t)warp * HID + lane] = __float2half_rn(acc * g_dinv[warp]);
}

// ---------------- fused: aggr layer1 + bias + relu + GEMM2 -> g_hC ----------------
// agg1 = dinv * (self + sum gathers); h2pre = relu(agg1+b1)@W2; g_hC = half(h2pre*dinv)
__global__ void k_aggr_gemm2(const float* __restrict__ b1, const float* __restrict__ W2) {
    int node = (blockIdx.x * blockDim.x + threadIdx.x) >> 5;
    int lane = threadIdx.x & 31;
    if (node >= N_NODES) return;
    int beg = g_rowptr[node];
    int deg = g_deg[node];
    const __half* __restrict__ src = g_hA;
    float acc = __half2float(src[(size_t)node * HID + lane]);   // self-loop
    int j = 0;
    for (; j + 4 <= deg; j += 4) {
        int s0 = g_csr_src[beg + j + 0];
        int s1 = g_csr_src[beg + j + 1];
        int s2 = g_csr_src[beg + j + 2];
        int s3 = g_csr_src[beg + j + 3];
        float a0 = __half2float(src[(size_t)s0 * HID + lane]);
        float a1 = __half2float(src[(size_t)s1 * HID + lane]);
        float a2 = __half2float(src[(size_t)s2 * HID + lane]);
        float a3 = __half2float(src[(size_t)s3 * HID + lane]);
        acc += (a0 + a1) + (a2 + a3);
    }
    for (; j < deg; j++)
        acc += __half2float(src[(size_t)g_csr_src[beg + j] * HID + lane]);
    float di = g_dinv[node];
    float v = fmaxf(acc * di + b1[lane], 0.0f);   // agg1 + b1, relu
    float o = 0.0f;
#pragma unroll
    for (int k = 0; k < HID; k++)
        o = fmaf(__shfl_sync(0xffffffffu, v, k), W2[k * HID + lane], o);
    g_hC[(size_t)node * HID + lane] = __float2half_rn(o * di);
}

// ---------------- fused: aggr layer2 + pool (red.v4 into g_sums) ----------------
__global__ void k_aggr_pool(const int* __restrict__ batch) {
    int node = (blockIdx.x * blockDim.x + threadIdx.x) >> 5;
    int lane = threadIdx.x & 31;
    if (node >= N_NODES) return;
    int beg = g_rowptr[node];
    int deg = g_deg[node];
    const __half* __restrict__ src = g_hC;
    float acc = __half2float(src[(size_t)node * HID + lane]);   // self-loop
    int j = 0;
    for (; j + 4 <= deg; j += 4) {
        int s0 = g_csr_src[beg + j + 0];
        int s1 = g_csr_src[beg + j + 1];
        int s2 = g_csr_src[beg + j + 2];
        int s3 = g_csr_src[beg + j + 3];
        float a0 = __half2float(src[(size_t)s0 * HID + lane]);
        float a1 = __half2float(src[(size_t)s1 * HID + lane]);
        float a2 = __half2float(src[(size_t)s2 * HID + lane]);
        float a3 = __half2float(src[(size_t)s3 * HID + lane]);
        acc += (a0 + a1) + (a2 + a3);
    }
    for (; j < deg; j++)
        acc += __half2float(src[(size_t)g_csr_src[beg + j] * HID + lane]);
    float t = acc * g_dinv[node];                // agg2 (bias reconstructed in MLP)
    int g = batch[node];
    float v1 = __shfl_down_sync(0xffffffffu, t, 1);
    float v2 = __shfl_down_sync(0xffffffffu, t, 2);
    float v3 = __shfl_down_sync(0xffffffffu, t, 3);
    if ((lane & 3) == 0)
        red_add_v4(&g_sums[(size_t)g * HID + lane], t, v1, v2, v3);
    if (lane == 0)
        red_add_f32(&g_cnt[g], 1.0f);
}

// ---------------- MLP head ----------------
__global__ void k_mlp(const float* __restrict__ b2,
                      const float* __restrict__ fcW1, const float* __restrict__ fcb1,
                      const float* __restrict__ fcW2, const float* __restrict__ fcb2,
                      float* __restrict__ out) {
    int warp = (blockIdx.x * blockDim.x + threadIdx.x) >> 5;
    int lane = threadIdx.x & 31;
    if (warp >= N_GRAPHS) return;
    float cnt = g_cnt[warp];
    float inv = 1.0f / fmaxf(cnt, 1.0f);
    // pooled = (sum(agg2) + cnt*b2) / max(cnt,1)  == mean(agg2 + b2)
    float p = (g_sums[(size_t)warp * HID + lane] + cnt * b2[lane]) * inv;
    float acc = fcb1[lane];
#pragma unroll
    for (int k = 0; k < HID; k++)
        acc = fmaf(__shfl_sync(0xffffffffu, p, k), fcW1[k * HID + lane], acc);
    acc = fmaxf(acc, 0.0f);
    float o = acc * fcW2[lane];
#pragma unroll
    for (int off = 16; off > 0; off >>= 1)
        o += __shfl_xor_sync(0xffffffffu, o, off);
    if (lane == 0) out[warp] = o + fcb2[0];
}

// ---------------- launch ----------------
extern "C" void kernel_launch(void* const* d_in, const int* in_sizes, int n_in,
                              void* d_out, int out_size) {
    const float* x     = (const float*)d_in[0];
    const int*   ei    = (const int*)  d_in[1];
    const int*   batch = (const int*)  d_in[2];
    const float* W1    = (const float*)d_in[3];
    const float* b1    = (const float*)d_in[4];
    const float* W2    = (const float*)d_in[5];
    const float* b2    = (const float*)d_in[6];
    const float* fcW1  = (const float*)d_in[7];
    const float* fcb1  = (const float*)d_in[8];
    const float* fcW2  = (const float*)d_in[9];
    const float* fcb2  = (const float*)d_in[10];
    float* out = (float*)d_out;

    const int TB = 256;
    const int node_grid = (N_NODES + TB - 1) / TB;
    const int edge_grid = (N_EDGES + TB - 1) / TB;
    const int warp_grid = (N_NODES * 32 + TB - 1) / TB;

    // CSR build (same topology for both layers)
    k_zero     <<<(N_GRAPHS * HID + TB - 1) / TB, TB>>>();
    k_count_deg<<<edge_grid, TB>>>(ei);
    k_scan1    <<<N_SCAN_BLOCKS, SCAN_BLK>>>();
    k_scan2    <<<1, 1024>>>();
    k_scan3    <<<node_grid, TB>>>();
    k_fill     <<<edge_grid, TB>>>(ei);

    // fused two-layer GCN + pooling
    k_gemm1     <<<warp_grid, TB>>>(x, W1);
    k_aggr_gemm2<<<warp_grid, TB>>>(b1, W2);
    k_aggr_pool <<<warp_grid, TB>>>(batch);
    k_mlp       <<<(N_GRAPHS * 32 + TB - 1) / TB, TB>>>(b2, fcW1, fcb1, fcW2, fcb2, out);
}

// round 6
// speedup vs baseline: 1.7545x; 1.1428x over previous
#include <cuda_runtime.h>
#include <cuda_fp16.h>

#define N_NODES 400000
#define N_EDGES 6400000
#define N_GRAPHS 20000
#define F_IN 11
#define HID 32

#define SCAN_BLK 512
#define N_SCAN_BLOCKS ((N_NODES + SCAN_BLK - 1) / SCAN_BLK)   // 782

// ---------------- scratch (static device globals; no allocs) ----------------
__device__ __align__(16) __half g_hA[(size_t)N_NODES * HID];   // layer-1 gather src (h1*dinv, fp16)
__device__ __align__(16) __half g_hC[(size_t)N_NODES * HID];   // layer-2 gather src (h2*dinv, fp16)
__device__ float g_dinv[N_NODES];
__device__ int   g_deg[N_NODES];          // edge-only in-degree
__device__ int   g_rowptr[N_NODES];
__device__ int   g_cursor[N_NODES];
__device__ int   g_partial[N_SCAN_BLOCKS];
__device__ int   g_csr_src[N_EDGES];
__device__ __align__(16) float g_sums[(size_t)N_GRAPHS * HID];
__device__ float g_cnt[N_GRAPHS];

// ---------------- helpers ----------------
__device__ __forceinline__ void red_add_v4(float* p, float a, float b, float c, float d) {
    asm volatile("red.global.add.v4.f32 [%0], {%1,%2,%3,%4};"
                 :: "l"(p), "f"(a), "f"(b), "f"(c), "f"(d) : "memory");
}
__device__ __forceinline__ void red_add_f32(float* p, float v) {
    asm volatile("red.global.add.f32 [%0], %1;" :: "l"(p), "f"(v) : "memory");
}

// ---------------- init / histogram ----------------
__global__ void k_zero() {
    int t = blockIdx.x * blockDim.x + threadIdx.x;
    if (t < N_GRAPHS * HID) g_sums[t] = 0.0f;
    if (t < N_GRAPHS)       g_cnt[t]  = 0.0f;
    if (t < N_NODES)        g_deg[t]  = 0;
}

// 4 edges per thread, int4 read of dst
__global__ void k_count_deg(const int* __restrict__ ei) {
    int t = blockIdx.x * blockDim.x + threadIdx.x;
    int e = t * 4;
    if (e >= N_EDGES) return;
    const int4 d = *(const int4*)&ei[N_EDGES + e];
    atomicAdd(&g_deg[d.x], 1);
    atomicAdd(&g_deg[d.y], 1);
    atomicAdd(&g_deg[d.z], 1);
    atomicAdd(&g_deg[d.w], 1);
}

// ---------------- exclusive scan over g_deg -> g_rowptr ----------------
__global__ void k_scan1() {
    __shared__ int wsum[SCAN_BLK / 32];
    int i = blockIdx.x * SCAN_BLK + threadIdx.x;
    int lane = threadIdx.x & 31, w = threadIdx.x >> 5;
    int v = (i < N_NODES) ? g_deg[i] : 0;
    int inc = v;
#pragma unroll
    for (int d = 1; d < 32; d <<= 1) {
        int t = __shfl_up_sync(0xffffffffu, inc, d);
        if (lane >= d) inc += t;
    }
    if (lane == 31) wsum[w] = inc;
    __syncthreads();
    if (threadIdx.x < SCAN_BLK / 32) {
        int s = wsum[threadIdx.x];
        int si = s;
#pragma unroll
        for (int d = 1; d < SCAN_BLK / 32; d <<= 1) {
            int t = __shfl_up_sync(0x0000ffffu, si, d);
            if ((int)threadIdx.x >= d) si += t;
        }
        wsum[threadIdx.x] = si - s;
        if (threadIdx.x == SCAN_BLK / 32 - 1) g_partial[blockIdx.x] = si;
    }
    __syncthreads();
    if (i < N_NODES) g_rowptr[i] = inc - v + wsum[w];
}

__global__ void k_scan2() {
    __shared__ int wsum[32];
    int tid = threadIdx.x, lane = tid & 31, w = tid >> 5;
    int v = (tid < N_SCAN_BLOCKS) ? g_partial[tid] : 0;
    int inc = v;
#pragma unroll
    for (int d = 1; d < 32; d <<= 1) {
        int t = __shfl_up_sync(0xffffffffu, inc, d);
        if (lane >= d) inc += t;
    }
    if (lane == 31) wsum[w] = inc;
    __syncthreads();
    if (tid < 32) {
        int s = wsum[tid];
        int si = s;
#pragma unroll
        for (int d = 1; d < 32; d <<= 1) {
            int t = __shfl_up_sync(0xffffffffu, si, d);
            if (tid >= d) si += t;
        }
        wsum[tid] = si - s;
    }
    __syncthreads();
    if (tid < N_SCAN_BLOCKS) g_partial[tid] = inc - v + wsum[w];
}

__global__ void k_scan3() {
    int i = blockIdx.x * blockDim.x + threadIdx.x;
    if (i >= N_NODES) return;
    int rp = g_rowptr[i] + g_partial[i / SCAN_BLK];
    g_rowptr[i] = rp;
    g_cursor[i] = rp;
    g_dinv[i] = rsqrtf((float)(g_deg[i] + 1));
}

// 4 edges per thread, int4 reads of src/dst
__global__ void k_fill(const int* __restrict__ ei) {
    int t = blockIdx.x * blockDim.x + threadIdx.x;
    int e = t * 4;
    if (e >= N_EDGES) return;
    const int4 s = *(const int4*)&ei[e];
    const int4 d = *(const int4*)&ei[N_EDGES + e];
    g_csr_src[atomicAdd(&g_cursor[d.x], 1)] = s.x;
    g_csr_src[atomicAdd(&g_cursor[d.y], 1)] = s.y;
    g_csr_src[atomicAdd(&g_cursor[d.z], 1)] = s.z;
    g_csr_src[atomicAdd(&g_cursor[d.w], 1)] = s.w;
}

// ---------------- layer-1 node GEMM: g_hA = half((x @ W1) * dinv) ----------------
__global__ void k_gemm1(const float* __restrict__ x, const float* __restrict__ W1) {
    int warp = (blockIdx.x * blockDim.x + threadIdx.x) >> 5;
    int lane = threadIdx.x & 31;
    if (warp >= N_NODES) return;
    float xi = (lane < F_IN) ? x[warp * F_IN + lane] : 0.0f;
    float acc = 0.0f;
#pragma unroll
    for (int k = 0; k < F_IN; k++)
        acc = fmaf(__shfl_sync(0xffffffffu, xi, k), W1[k * HID + lane], acc);
    g_hA[(size_t)warp * HID + lane] = __float2half_rn(acc * g_dinv[warp]);
}

// ---------------- fused: aggr L1 (4 nodes/warp) + bias + relu + GEMM2 -> g_hC ----
// 8-lane group g owns node warp*4+g; lane q=lane&7 covers features 4q..4q+3.
__global__ void k_aggr_gemm2(const float* __restrict__ b1, const float* __restrict__ W2) {
    const unsigned FULL = 0xffffffffu;
    int warp = (blockIdx.x * blockDim.x + threadIdx.x) >> 5;
    int lane = threadIdx.x & 31;
    if (warp * 4 >= N_NODES) return;
    int g = lane >> 3, q = lane & 7;
    int node = warp * 4 + g;

    // W2 column for this lane (reused for all 4 nodes) + bias register
    float wcol[HID];
#pragma unroll
    for (int k = 0; k < HID; k++) wcol[k] = W2[k * HID + lane];
    float b1v = b1[lane];

    int beg = g_rowptr[node];
    int deg = g_deg[node];
    float di = g_dinv[node];

    float a0, a1, a2, a3;
    {   // self-loop row
        uint2 p = *(const uint2*)&g_hA[(size_t)node * HID + q * 4];
        float2 f0 = __half22float2(*(const __half2*)&p.x);
        float2 f1 = __half22float2(*(const __half2*)&p.y);
        a0 = f0.x; a1 = f0.y; a2 = f1.x; a3 = f1.y;
    }
#pragma unroll 4
    for (int t = 0; t < deg; t++) {
        int idx = __ldg(&g_csr_src[beg + t]);
        uint2 p = *(const uint2*)&g_hA[(size_t)idx * HID + q * 4];
        float2 f0 = __half22float2(*(const __half2*)&p.x);
        float2 f1 = __half22float2(*(const __half2*)&p.y);
        a0 += f0.x; a1 += f0.y; a2 += f1.x; a3 += f1.y;
    }
    __syncwarp();

    float di0 = __shfl_sync(FULL, di, 0);
    float di1 = __shfl_sync(FULL, di, 8);
    float di2 = __shfl_sync(FULL, di, 16);
    float di3 = __shfl_sync(FULL, di, 24);
    float o0 = 0.0f, o1 = 0.0f, o2 = 0.0f, o3 = 0.0f;
#pragma unroll
    for (int k = 0; k < HID; k++) {
        float ar = (k & 3) == 0 ? a0 : (k & 3) == 1 ? a1 : (k & 3) == 2 ? a2 : a3;
        float bk = __shfl_sync(FULL, b1v, k);
        int sl = k >> 2;
        float w = wcol[k];
        float v0 = fmaxf(fmaf(__shfl_sync(FULL, ar, sl),      di0, bk), 0.0f);
        float v1 = fmaxf(fmaf(__shfl_sync(FULL, ar, 8 + sl),  di1, bk), 0.0f);
        float v2 = fmaxf(fmaf(__shfl_sync(FULL, ar, 16 + sl), di2, bk), 0.0f);
        float v3 = fmaxf(fmaf(__shfl_sync(FULL, ar, 24 + sl), di3, bk), 0.0f);
        o0 = fmaf(v0, w, o0);
        o1 = fmaf(v1, w, o1);
        o2 = fmaf(v2, w, o2);
        o3 = fmaf(v3, w, o3);
    }
    size_t base = (size_t)(warp * 4) * HID + lane;
    g_hC[base + 0 * HID] = __float2half_rn(o0 * di0);
    g_hC[base + 1 * HID] = __float2half_rn(o1 * di1);
    g_hC[base + 2 * HID] = __float2half_rn(o2 * di2);
    g_hC[base + 3 * HID] = __float2half_rn(o3 * di3);
}

// ---------------- fused: aggr L2 (4 nodes/warp) + pool ----------------
__global__ void k_aggr_pool(const int* __restrict__ batch) {
    int warp = (blockIdx.x * blockDim.x + threadIdx.x) >> 5;
    int lane = threadIdx.x & 31;
    if (warp * 4 >= N_NODES) return;
    int g = lane >> 3, q = lane & 7;
    int node = warp * 4 + g;

    int beg = g_rowptr[node];
    int deg = g_deg[node];
    float di = g_dinv[node];

    float a0, a1, a2, a3;
    {
        uint2 p = *(const uint2*)&g_hC[(size_t)node * HID + q * 4];
        float2 f0 = __half22float2(*(const __half2*)&p.x);
        float2 f1 = __half22float2(*(const __half2*)&p.y);
        a0 = f0.x; a1 = f0.y; a2 = f1.x; a3 = f1.y;
    }
#pragma unroll 4
    for (int t = 0; t < deg; t++) {
        int idx = __ldg(&g_csr_src[beg + t]);
        uint2 p = *(const uint2*)&g_hC[(size_t)idx * HID + q * 4];
        float2 f0 = __half22float2(*(const __half2*)&p.x);
        float2 f1 = __half22float2(*(const __half2*)&p.y);
        a0 += f0.x; a1 += f0.y; a2 += f1.x; a3 += f1.y;
    }
    __syncwarp();

    int grp = batch[node];
    red_add_v4(&g_sums[(size_t)grp * HID + q * 4], a0 * di, a1 * di, a2 * di, a3 * di);
    if (q == 0) red_add_f32(&g_cnt[grp], 1.0f);
}

// ---------------- MLP head ----------------
__global__ void k_mlp(const float* __restrict__ b2,
                      const float* __restrict__ fcW1, const float* __restrict__ fcb1,
                      const float* __restrict__ fcW2, const float* __restrict__ fcb2,
                      float* __restrict__ out) {
    int warp = (blockIdx.x * blockDim.x + threadIdx.x) >> 5;
    int lane = threadIdx.x & 31;
    if (warp >= N_GRAPHS) return;
    float cnt = g_cnt[warp];
    float inv = 1.0f / fmaxf(cnt, 1.0f);
    // pooled = (sum(agg2) + cnt*b2) / max(cnt,1)  == mean(agg2 + b2)
    float p = (g_sums[(size_t)warp * HID + lane] + cnt * b2[lane]) * inv;
    float acc = fcb1[lane];
#pragma unroll
    for (int k = 0; k < HID; k++)
        acc = fmaf(__shfl_sync(0xffffffffu, p, k), fcW1[k * HID + lane], acc);
    acc = fmaxf(acc, 0.0f);
    float o = acc * fcW2[lane];
#pragma unroll
    for (int off = 16; off > 0; off >>= 1)
        o += __shfl_xor_sync(0xffffffffu, o, off);
    if (lane == 0) out[warp] = o + fcb2[0];
}

// ---------------- launch ----------------
extern "C" void kernel_launch(void* const* d_in, const int* in_sizes, int n_in,
                              void* d_out, int out_size) {
    const float* x     = (const float*)d_in[0];
    const int*   ei    = (const int*)  d_in[1];
    const int*   batch = (const int*)  d_in[2];
    const float* W1    = (const float*)d_in[3];
    const float* b1    = (const float*)d_in[4];
    const float* W2    = (const float*)d_in[5];
    const float* b2    = (const float*)d_in[6];
    const float* fcW1  = (const float*)d_in[7];
    const float* fcb1  = (const float*)d_in[8];
    const float* fcW2  = (const float*)d_in[9];
    const float* fcb2  = (const float*)d_in[10];
    float* out = (float*)d_out;

    const int TB = 256;
    const int node_grid  = (N_NODES + TB - 1) / TB;
    const int edge4_grid = (N_EDGES / 4 + TB - 1) / TB;
    const int warp_grid  = (N_NODES * 32 + TB - 1) / TB;          // warp per node
    const int warp4_grid = ((N_NODES / 4) * 32 + TB - 1) / TB;    // warp per 4 nodes

    // CSR build (same topology for both layers)
    k_zero     <<<(N_GRAPHS * HID + TB - 1) / TB, TB>>>();
    k_count_deg<<<edge4_grid, TB>>>(ei);
    k_scan1    <<<N_SCAN_BLOCKS, SCAN_BLK>>>();
    k_scan2    <<<1, 1024>>>();
    k_scan3    <<<node_grid, TB>>>();
    k_fill     <<<edge4_grid, TB>>>(ei);

    // fused two-layer GCN + pooling
    k_gemm1     <<<warp_grid, TB>>>(x, W1);
    k_aggr_gemm2<<<warp4_grid, TB>>>(b1, W2);
    k_aggr_pool <<<warp4_grid, TB>>>(batch);
    k_mlp       <<<(N_GRAPHS * 32 + TB - 1) / TB, TB>>>(b2, fcW1, fcb1, fcW2, fcb2, out);
}

// round 8
// speedup vs baseline: 2.0651x; 1.1770x over previous
#include <cuda_runtime.h>
#include <cuda_fp16.h>

#define N_NODES 400000
#define N_EDGES 6400000
#define N_GRAPHS 20000
#define F_IN 11
#define HID 32
#define CAP 64   // padded CSR row capacity; deg ~ Poisson(16), P(>=64) ~ 0

// ---------------- scratch (static device globals; no allocs) ----------------
__device__ __align__(16) __half g_hA[(size_t)N_NODES * HID];   // layer-1 gather src (h1*dinv, fp16)
__device__ __align__(16) __half g_hC[(size_t)N_NODES * HID];   // layer-2 gather src (h2*dinv, fp16)
__device__ float g_dinv[N_NODES];
__device__ int   g_cursor[N_NODES];                 // fill cursor; == deg after k_fill
__device__ int   g_csr_pad[(size_t)N_NODES * CAP];  // padded CSR (src indices)
__device__ __align__(16) float g_sums[(size_t)N_GRAPHS * HID];
__device__ float g_cnt[N_GRAPHS];

// ---------------- helpers ----------------
__device__ __forceinline__ void red_add_v4(float* p, float a, float b, float c, float d) {
    asm volatile("red.global.add.v4.f32 [%0], {%1,%2,%3,%4};"
                 :: "l"(p), "f"(a), "f"(b), "f"(c), "f"(d) : "memory");
}
__device__ __forceinline__ void red_add_f32(float* p, float v) {
    asm volatile("red.global.add.f32 [%0], %1;" :: "l"(p), "f"(v) : "memory");
}

// ---------------- init ----------------
__global__ void k_zero() {
    int t = blockIdx.x * blockDim.x + threadIdx.x;
    if (t < N_GRAPHS * HID) g_sums[t]   = 0.0f;
    if (t < N_GRAPHS)       g_cnt[t]    = 0.0f;
    if (t < N_NODES)        g_cursor[t] = 0;
}

// padded-CSR fill: 4 edges per thread, int4 reads of src/dst
__global__ void k_fill(const int* __restrict__ ei) {
    int t = blockIdx.x * blockDim.x + threadIdx.x;
    int e = t * 4;
    if (e >= N_EDGES) return;
    const int4 s = *(const int4*)&ei[e];
    const int4 d = *(const int4*)&ei[N_EDGES + e];
    g_csr_pad[(size_t)d.x * CAP + atomicAdd(&g_cursor[d.x], 1)] = s.x;
    g_csr_pad[(size_t)d.y * CAP + atomicAdd(&g_cursor[d.y], 1)] = s.y;
    g_csr_pad[(size_t)d.z * CAP + atomicAdd(&g_cursor[d.z], 1)] = s.z;
    g_csr_pad[(size_t)d.w * CAP + atomicAdd(&g_cursor[d.w], 1)] = s.w;
}

// ---------------- layer-1 node GEMM + dinv: g_hA = half((x @ W1) * dinv) --------
__global__ void k_gemm1(const float* __restrict__ x, const float* __restrict__ W1) {
    int warp = (blockIdx.x * blockDim.x + threadIdx.x) >> 5;
    int lane = threadIdx.x & 31;
    if (warp >= N_NODES) return;
    float xi = (lane < F_IN) ? x[warp * F_IN + lane] : 0.0f;
    float acc = 0.0f;
#pragma unroll
    for (int k = 0; k < F_IN; k++)
        acc = fmaf(__shfl_sync(0xffffffffu, xi, k), W1[k * HID + lane], acc);
    int deg = g_cursor[warp];                         // broadcast load
    float di = rsqrtf((float)(deg + 1));              // +1 self-loop
    if (lane == 0) g_dinv[warp] = di;
    g_hA[(size_t)warp * HID + lane] = __float2half_rn(acc * di);
}

// ---------------- fused: aggr L1 (4 nodes/warp) + bias + relu + GEMM2 -> g_hC ----
// 8-lane group g owns node warp*4+g; lane q=lane&7 covers features 4q..4q+3.
__global__ void k_aggr_gemm2(const float* __restrict__ b1, const float* __restrict__ W2) {
    const unsigned FULL = 0xffffffffu;
    int warp = (blockIdx.x * blockDim.x + threadIdx.x) >> 5;
    int lane = threadIdx.x & 31;
    if (warp * 4 >= N_NODES) return;
    int g = lane >> 3, q = lane & 7;
    int node = warp * 4 + g;

    // W2 column for this lane (reused for all 4 nodes) + bias register
    float wcol[HID];
#pragma unroll
    for (int k = 0; k < HID; k++) wcol[k] = W2[k * HID + lane];
    float b1v = b1[lane];

    size_t beg = (size_t)node * CAP;
    int deg = g_cursor[node];
    float di = g_dinv[node];

    float a0, a1, a2, a3;
    {   // self-loop row
        uint2 p = *(const uint2*)&g_hA[(size_t)node * HID + q * 4];
        float2 f0 = __half22float2(*(const __half2*)&p.x);
        float2 f1 = __half22float2(*(const __half2*)&p.y);
        a0 = f0.x; a1 = f0.y; a2 = f1.x; a3 = f1.y;
    }
#pragma unroll 4
    for (int t = 0; t < deg; t++) {
        int idx = __ldg(&g_csr_pad[beg + t]);
        uint2 p = *(const uint2*)&g_hA[(size_t)idx * HID + q * 4];
        float2 f0 = __half22float2(*(const __half2*)&p.x);
        float2 f1 = __half22float2(*(const __half2*)&p.y);
        a0 += f0.x; a1 += f0.y; a2 += f1.x; a3 += f1.y;
    }
    __syncwarp();

    float di0 = __shfl_sync(FULL, di, 0);
    float di1 = __shfl_sync(FULL, di, 8);
    float di2 = __shfl_sync(FULL, di, 16);
    float di3 = __shfl_sync(FULL, di, 24);
    float o0 = 0.0f, o1 = 0.0f, o2 = 0.0f, o3 = 0.0f;
#pragma unroll
    for (int k = 0; k < HID; k++) {
        float ar = (k & 3) == 0 ? a0 : (k & 3) == 1 ? a1 : (k & 3) == 2 ? a2 : a3;
        float bk = __shfl_sync(FULL, b1v, k);
        int sl = k >> 2;
        float w = wcol[k];
        float v0 = fmaxf(fmaf(__shfl_sync(FULL, ar, sl),      di0, bk), 0.0f);
        float v1 = fmaxf(fmaf(__shfl_sync(FULL, ar, 8 + sl),  di1, bk), 0.0f);
        float v2 = fmaxf(fmaf(__shfl_sync(FULL, ar, 16 + sl), di2, bk), 0.0f);
        float v3 = fmaxf(fmaf(__shfl_sync(FULL, ar, 24 + sl), di3, bk), 0.0f);
        o0 = fmaf(v0, w, o0);
        o1 = fmaf(v1, w, o1);
        o2 = fmaf(v2, w, o2);
        o3 = fmaf(v3, w, o3);
    }
    size_t base = (size_t)(warp * 4) * HID + lane;
    g_hC[base + 0 * HID] = __float2half_rn(o0 * di0);
    g_hC[base + 1 * HID] = __float2half_rn(o1 * di1);
    g_hC[base + 2 * HID] = __float2half_rn(o2 * di2);
    g_hC[base + 3 * HID] = __float2half_rn(o3 * di3);
}

// ---------------- fused: aggr L2 (4 nodes/warp) + pool ----------------
__global__ void k_aggr_pool(const int* __restrict__ batch) {
    int warp = (blockIdx.x * blockDim.x + threadIdx.x) >> 5;
    int lane = threadIdx.x & 31;
    if (warp * 4 >= N_NODES) return;
    int g = lane >> 3, q = lane & 7;
    int node = warp * 4 + g;

    size_t beg = (size_t)node * CAP;
    int deg = g_cursor[node];
    float di = g_dinv[node];

    float a0, a1, a2, a3;
    {
        uint2 p = *(const uint2*)&g_hC[(size_t)node * HID + q * 4];
        float2 f0 = __half22float2(*(const __half2*)&p.x);
        float2 f1 = __half22float2(*(const __half2*)&p.y);
        a0 = f0.x; a1 = f0.y; a2 = f1.x; a3 = f1.y;
    }
#pragma unroll 4
    for (int t = 0; t < deg; t++) {
        int idx = __ldg(&g_csr_pad[beg + t]);
        uint2 p = *(const uint2*)&g_hC[(size_t)idx * HID + q * 4];
        float2 f0 = __half22float2(*(const __half2*)&p.x);
        float2 f1 = __half22float2(*(const __half2*)&p.y);
        a0 += f0.x; a1 += f0.y; a2 += f1.x; a3 += f1.y;
    }
    __syncwarp();

    int grp = batch[node];
    red_add_v4(&g_sums[(size_t)grp * HID + q * 4], a0 * di, a1 * di, a2 * di, a3 * di);
    if (q == 0) red_add_f32(&g_cnt[grp], 1.0f);
}

// ---------------- MLP head ----------------
__global__ void k_mlp(const float* __restrict__ b2,
                      const float* __restrict__ fcW1, const float* __restrict__ fcb1,
                      const float* __restrict__ fcW2, const float* __restrict__ fcb2,
                      float* __restrict__ out) {
    int warp = (blockIdx.x * blockDim.x + threadIdx.x) >> 5;
    int lane = threadIdx.x & 31;
    if (warp >= N_GRAPHS) return;
    float cnt = g_cnt[warp];
    float inv = 1.0f / fmaxf(cnt, 1.0f);
    // pooled = (sum(agg2) + cnt*b2) / max(cnt,1)  == mean(agg2 + b2)
    float p = (g_sums[(size_t)warp * HID + lane] + cnt * b2[lane]) * inv;
    float acc = fcb1[lane];
#pragma unroll
    for (int k = 0; k < HID; k++)
        acc = fmaf(__shfl_sync(0xffffffffu, p, k), fcW1[k * HID + lane], acc);
    acc = fmaxf(acc, 0.0f);
    float o = acc * fcW2[lane];
#pragma unroll
    for (int off = 16; off > 0; off >>= 1)
        o += __shfl_xor_sync(0xffffffffu, o, off);
    if (lane == 0) out[warp] = o + fcb2[0];
}

// ---------------- launch ----------------
extern "C" void kernel_launch(void* const* d_in, const int* in_sizes, int n_in,
                              void* d_out, int out_size) {
    const float* x     = (const float*)d_in[0];
    const int*   ei    = (const int*)  d_in[1];
    const int*   batch = (const int*)  d_in[2];
    const float* W1    = (const float*)d_in[3];
    const float* b1    = (const float*)d_in[4];
    const float* W2    = (const float*)d_in[5];
    const float* b2    = (const float*)d_in[6];
    const float* fcW1  = (const float*)d_in[7];
    const float* fcb1  = (const float*)d_in[8];
    const float* fcW2  = (const float*)d_in[9];
    const float* fcb2  = (const float*)d_in[10];
    float* out = (float*)d_out;

    const int TB = 256;
    const int edge4_grid = (N_EDGES / 4 + TB - 1) / TB;
    const int warp_grid  = (N_NODES * 32 + TB - 1) / TB;          // warp per node
    const int warp4_grid = ((N_NODES / 4) * 32 + TB - 1) / TB;    // warp per 4 nodes

    // launch order fixed so ncu (-s 5, incl. 2 harness launches) profiles k_aggr_gemm2
    k_zero      <<<(N_GRAPHS * HID + TB - 1) / TB, TB>>>();          // 0
    k_fill      <<<edge4_grid, TB>>>(ei);                            // 1
    k_gemm1     <<<warp_grid, TB>>>(x, W1);                          // 2
    k_aggr_gemm2<<<warp4_grid, TB>>>(b1, W2);                        // 3  <- profiled
    k_aggr_pool <<<warp4_grid, TB>>>(batch);                         // 4
    k_mlp       <<<(N_GRAPHS * 32 + TB - 1) / TB, TB>>>(b2, fcW1, fcb1, fcW2, fcb2, out);
}

// round 9
// speedup vs baseline: 2.2156x; 1.0729x over previous
#include <cuda_runtime.h>
#include <cuda_fp16.h>

#define N_NODES 400000
#define N_EDGES 6400000
#define N_GRAPHS 20000
#define F_IN 11
#define HID 32
#define CAP 64   // padded CSR row capacity; deg ~ Poisson(16), P(>=64) ~ 0

// ---------------- scratch (static device globals; no allocs) ----------------
__device__ __align__(16) __half g_hA[(size_t)N_NODES * HID];   // layer-1 gather src (h1*dinv, fp16)
__device__ __align__(16) __half g_hC[(size_t)N_NODES * HID];   // layer-2 gather src (h2*dinv, fp16)
__device__ float g_dinv[N_NODES];
__device__ int   g_cursor[N_NODES];                 // fill cursor; == deg after k_fill
__device__ int   g_csr_pad[(size_t)N_NODES * CAP];  // padded CSR (src indices)
__device__ __align__(16) float g_sums[(size_t)N_GRAPHS * HID];
__device__ float g_cnt[N_GRAPHS];

// ---------------- helpers ----------------
__device__ __forceinline__ void red_add_v4(float* p, float a, float b, float c, float d) {
    asm volatile("red.global.add.v4.f32 [%0], {%1,%2,%3,%4};"
                 :: "l"(p), "f"(a), "f"(b), "f"(c), "f"(d) : "memory");
}
__device__ __forceinline__ void red_add_f32(float* p, float v) {
    asm volatile("red.global.add.f32 [%0], %1;" :: "l"(p), "f"(v) : "memory");
}

// ---------------- init ----------------
__global__ void k_zero() {
    int t = blockIdx.x * blockDim.x + threadIdx.x;
    if (t < N_GRAPHS * HID) g_sums[t]   = 0.0f;
    if (t < N_GRAPHS)       g_cnt[t]    = 0.0f;
    if (t < N_NODES)        g_cursor[t] = 0;
}

// padded-CSR fill: 4 edges per thread, int4 reads of src/dst
__global__ void k_fill(const int* __restrict__ ei) {
    int t = blockIdx.x * blockDim.x + threadIdx.x;
    int e = t * 4;
    if (e >= N_EDGES) return;
    const int4 s = *(const int4*)&ei[e];
    const int4 d = *(const int4*)&ei[N_EDGES + e];
    g_csr_pad[(size_t)d.x * CAP + atomicAdd(&g_cursor[d.x], 1)] = s.x;
    g_csr_pad[(size_t)d.y * CAP + atomicAdd(&g_cursor[d.y], 1)] = s.y;
    g_csr_pad[(size_t)d.z * CAP + atomicAdd(&g_cursor[d.z], 1)] = s.z;
    g_csr_pad[(size_t)d.w * CAP + atomicAdd(&g_cursor[d.w], 1)] = s.w;
}

// ---------------- layer-1 node GEMM + dinv: g_hA = half((x @ W1) * dinv) --------
__global__ void k_gemm1(const float* __restrict__ x, const float* __restrict__ W1) {
    int warp = (blockIdx.x * blockDim.x + threadIdx.x) >> 5;
    int lane = threadIdx.x & 31;
    if (warp >= N_NODES) return;
    float xi = (lane < F_IN) ? x[warp * F_IN + lane] : 0.0f;
    float acc = 0.0f;
#pragma unroll
    for (int k = 0; k < F_IN; k++)
        acc = fmaf(__shfl_sync(0xffffffffu, xi, k), W1[k * HID + lane], acc);
    int deg = g_cursor[warp];                         // broadcast load
    float di = rsqrtf((float)(deg + 1));              // +1 self-loop
    if (lane == 0) g_dinv[warp] = di;
    g_hA[(size_t)warp * HID + lane] = __float2half_rn(acc * di);
}

// ---------------- fused: aggr L1 (4 nodes/warp) + bias + relu + GEMM2 -> g_hC ----
// 8-lane group g owns node warp*4+g; lane q=lane&7 covers features 4q..4q+3.
// Warp-uniform degree loop with 8-ahead coalesced index prefetch; W2 in smem.
__global__ void __launch_bounds__(256, 6)
k_aggr_gemm2(const float* __restrict__ b1, const float* __restrict__ W2) {
    __shared__ float sW2[HID * HID];
    for (int i = threadIdx.x; i < HID * HID; i += 256) sW2[i] = W2[i];
    __syncthreads();

    const unsigned FULL = 0xffffffffu;
    int warp = (blockIdx.x * blockDim.x + threadIdx.x) >> 5;
    int lane = threadIdx.x & 31;
    if (warp * 4 >= N_NODES) return;
    int g = lane >> 3, q = lane & 7;
    int node = warp * 4 + g;

    size_t beg = (size_t)node * CAP;
    int deg = g_cursor[node];
    float di = g_dinv[node];

    // warp-max degree (deg uniform within 8-lane group; xor 8,16 spans groups)
    int maxdeg = deg;
    maxdeg = max(maxdeg, __shfl_xor_sync(FULL, maxdeg, 8));
    maxdeg = max(maxdeg, __shfl_xor_sync(FULL, maxdeg, 16));
    maxdeg = min(maxdeg, CAP);

    float a0, a1, a2, a3;
    {   // self-loop row
        uint2 p = *(const uint2*)&g_hA[(size_t)node * HID + q * 4];
        float2 f0 = __half22float2(*(const __half2*)&p.x);
        float2 f1 = __half22float2(*(const __half2*)&p.y);
        a0 = f0.x; a1 = f0.y; a2 = f1.x; a3 = f1.y;
    }

    int pre = 0;
    for (int t = 0; t < maxdeg; t++) {
        if ((t & 7) == 0)   // lane q prefetches index t+q of its group (coalesced 32B)
            pre = __ldg(&g_csr_pad[beg + t + q]);
        int idx = __shfl_sync(FULL, pre, (lane & 24) + (t & 7));
        if (t < deg) {
            uint2 p = *(const uint2*)&g_hA[(size_t)idx * HID + q * 4];
            float2 f0 = __half22float2(*(const __half2*)&p.x);
            float2 f1 = __half22float2(*(const __half2*)&p.y);
            a0 += f0.x; a1 += f0.y; a2 += f1.x; a3 += f1.y;
        }
    }

    // hoisted: v = relu(agg*di + b1)  (lane q owns features 4q..4q+3)
    float4 bq = ((const float4*)b1)[q];
    float v0 = fmaxf(fmaf(a0, di, bq.x), 0.0f);
    float v1 = fmaxf(fmaf(a1, di, bq.y), 0.0f);
    float v2 = fmaxf(fmaf(a2, di, bq.z), 0.0f);
    float v3 = fmaxf(fmaf(a3, di, bq.w), 0.0f);

    float di0 = __shfl_sync(FULL, di, 0);
    float di1 = __shfl_sync(FULL, di, 8);
    float di2 = __shfl_sync(FULL, di, 16);
    float di3 = __shfl_sync(FULL, di, 24);

    float o0 = 0.0f, o1 = 0.0f, o2 = 0.0f, o3 = 0.0f;
#pragma unroll
    for (int k = 0; k < HID; k++) {
        float vr = (k & 3) == 0 ? v0 : (k & 3) == 1 ? v1 : (k & 3) == 2 ? v2 : v3;
        int sl = k >> 2;
        float w = sW2[k * HID + lane];
        o0 = fmaf(__shfl_sync(FULL, vr, sl),      w, o0);
        o1 = fmaf(__shfl_sync(FULL, vr, 8 + sl),  w, o1);
        o2 = fmaf(__shfl_sync(FULL, vr, 16 + sl), w, o2);
        o3 = fmaf(__shfl_sync(FULL, vr, 24 + sl), w, o3);
    }
    size_t base = (size_t)(warp * 4) * HID + lane;
    g_hC[base + 0 * HID] = __float2half_rn(o0 * di0);
    g_hC[base + 1 * HID] = __float2half_rn(o1 * di1);
    g_hC[base + 2 * HID] = __float2half_rn(o2 * di2);
    g_hC[base + 3 * HID] = __float2half_rn(o3 * di3);
}

// ---------------- fused: aggr L2 (4 nodes/warp) + pool ----------------
__global__ void __launch_bounds__(256, 6)
k_aggr_pool(const int* __restrict__ batch) {
    const unsigned FULL = 0xffffffffu;
    int warp = (blockIdx.x * blockDim.x + threadIdx.x) >> 5;
    int lane = threadIdx.x & 31;
    if (warp * 4 >= N_NODES) return;
    int g = lane >> 3, q = lane & 7;
    int node = warp * 4 + g;

    size_t beg = (size_t)node * CAP;
    int deg = g_cursor[node];
    float di = g_dinv[node];

    int maxdeg = deg;
    maxdeg = max(maxdeg, __shfl_xor_sync(FULL, maxdeg, 8));
    maxdeg = max(maxdeg, __shfl_xor_sync(FULL, maxdeg, 16));
    maxdeg = min(maxdeg, CAP);

    float a0, a1, a2, a3;
    {
        uint2 p = *(const uint2*)&g_hC[(size_t)node * HID + q * 4];
        float2 f0 = __half22float2(*(const __half2*)&p.x);
        float2 f1 = __half22float2(*(const __half2*)&p.y);
        a0 = f0.x; a1 = f0.y; a2 = f1.x; a3 = f1.y;
    }

    int pre = 0;
    for (int t = 0; t < maxdeg; t++) {
        if ((t & 7) == 0)
            pre = __ldg(&g_csr_pad[beg + t + q]);
        int idx = __shfl_sync(FULL, pre, (lane & 24) + (t & 7));
        if (t < deg) {
            uint2 p = *(const uint2*)&g_hC[(size_t)idx * HID + q * 4];
            float2 f0 = __half22float2(*(const __half2*)&p.x);
            float2 f1 = __half22float2(*(const __half2*)&p.y);
            a0 += f0.x; a1 += f0.y; a2 += f1.x; a3 += f1.y;
        }
    }

    int grp = batch[node];
    red_add_v4(&g_sums[(size_t)grp * HID + q * 4], a0 * di, a1 * di, a2 * di, a3 * di);
    if (q == 0) red_add_f32(&g_cnt[grp], 1.0f);
}

// ---------------- MLP head ----------------
__global__ void k_mlp(const float* __restrict__ b2,
                      const float* __restrict__ fcW1, const float* __restrict__ fcb1,
                      const float* __restrict__ fcW2, const float* __restrict__ fcb2,
                      float* __restrict__ out) {
    int warp = (blockIdx.x * blockDim.x + threadIdx.x) >> 5;
    int lane = threadIdx.x & 31;
    if (warp >= N_GRAPHS) return;
    float cnt = g_cnt[warp];
    float inv = 1.0f / fmaxf(cnt, 1.0f);
    // pooled = (sum(agg2) + cnt*b2) / max(cnt,1)  == mean(agg2 + b2)
    float p = (g_sums[(size_t)warp * HID + lane] + cnt * b2[lane]) * inv;
    float acc = fcb1[lane];
#pragma unroll
    for (int k = 0; k < HID; k++)
        acc = fmaf(__shfl_sync(0xffffffffu, p, k), fcW1[k * HID + lane], acc);
    acc = fmaxf(acc, 0.0f);
    float o = acc * fcW2[lane];
#pragma unroll
    for (int off = 16; off > 0; off >>= 1)
        o += __shfl_xor_sync(0xffffffffu, o, off);
    if (lane == 0) out[warp] = o + fcb2[0];
}

// ---------------- launch ----------------
extern "C" void kernel_launch(void* const* d_in, const int* in_sizes, int n_in,
                              void* d_out, int out_size) {
    const float* x     = (const float*)d_in[0];
    const int*   ei    = (const int*)  d_in[1];
    const int*   batch = (const int*)  d_in[2];
    const float* W1    = (const float*)d_in[3];
    const float* b1    = (const float*)d_in[4];
    const float* W2    = (const float*)d_in[5];
    const float* b2    = (const float*)d_in[6];
    const float* fcW1  = (const float*)d_in[7];
    const float* fcb1  = (const float*)d_in[8];
    const float* fcW2  = (const float*)d_in[9];
    const float* fcb2  = (const float*)d_in[10];
    float* out = (float*)d_out;

    const int TB = 256;
    const int edge4_grid = (N_EDGES / 4 + TB - 1) / TB;
    const int warp_grid  = (N_NODES * 32 + TB - 1) / TB;          // warp per node
    const int warp4_grid = ((N_NODES / 4) * 32 + TB - 1) / TB;    // warp per 4 nodes

    // launch order fixed so ncu (-s 5, incl. 2 harness launches) profiles k_aggr_gemm2
    k_zero      <<<(N_GRAPHS * HID + TB - 1) / TB, TB>>>();          // 0
    k_fill      <<<edge4_grid, TB>>>(ei);                            // 1
    k_gemm1     <<<warp_grid, TB>>>(x, W1);                          // 2
    k_aggr_gemm2<<<warp4_grid, TB>>>(b1, W2);                        // 3  <- profiled
    k_aggr_pool <<<warp4_grid, TB>>>(batch);                         // 4
    k_mlp       <<<(N_GRAPHS * 32 + TB - 1) / TB, TB>>>(b2, fcW1, fcb1, fcW2, fcb2, out);
}